// round 10
// baseline (speedup 1.0000x reference)
#include <cuda_runtime.h>

#define BB   64
#define HH   384
#define NPLT 16
#define NG   25
#define CAND 625   // NG*NG
#define LF   400   // HH + NPLT
#define JS   4     // j-chunks in k_base
#define JCH  96    // j per chunk (4*96 = 384)
#define TROW 28    // padded table row (floats): 7 tiles x 4, 112B rows

#define LOG2E_F  1.4426950408889634f
#define LOG2PI_F 1.8378770664093453f

// persistent scratch (allocation-free rule: __device__ globals)
__device__ float g_xlim[NG];
__device__ float g_ylim[NG];
__device__ float g_Spart[JS][BB * CAND];

__device__ __forceinline__ float ex2f(float x) {
    float r;
    asm("ex2.approx.ftz.f32 %0, %1;" : "=f"(r) : "f"(x));
    return r;
}
__device__ __forceinline__ unsigned redux_min_u32(unsigned v) {
    unsigned d;
    asm("redux.sync.min.u32 %0, %1, 0xffffffff;" : "=r"(d) : "r"(v));
    return d;
}

// ---------------------------------------------------------------------------
// Kernel 1: factorized base-S partials (unchanged from R9, measured 10.4us).
//   S[b][k] = sum_j Bx[j][kx] * Ay[j][ky],
//   Bx = exp(beta*t_j*log2e - c2*dx^2), Ay = exp(-c2*dy^2).
// grid (4 j-chunks, 64 batches), 192 threads; 175 compute threads own a
// 4(kx) x 1(ky) register tile. Every block recomputes grid bounds:
//   minx/maxx = min/max over BOTH coords of history POINT 0 (all batches)
//   miny/maxy = min/max over BOTH coords of history POINT 1 (all batches)
// ---------------------------------------------------------------------------
__global__ __launch_bounds__(192, 2)
void k_base(const float* __restrict__ itime,
            const float* __restrict__ hist,
            const float* __restrict__ beta_p,
            const float* __restrict__ logsig_p) {
    __shared__ __align__(16) float Bx[JCH * TROW];
    __shared__ __align__(16) float Ay[JCH * TROW];
    __shared__ float sxa[JCH], sya[JCH], sbta[JCH];
    __shared__ float xl[NG], yl[NG];
    __shared__ float bounds[4];

    const int jc = blockIdx.x;
    const int b  = blockIdx.y;
    const int t  = threadIdx.x;
    const int w  = t >> 5, lane = t & 31;

    if (w < 2) {
        float a0 = hist[lane * (HH * 2) + 2 * w + 0];
        float a1 = hist[lane * (HH * 2) + 2 * w + 1];
        float b0 = hist[(lane + 32) * (HH * 2) + 2 * w + 0];
        float b1 = hist[(lane + 32) * (HH * 2) + 2 * w + 1];
        float mn = fminf(fminf(a0, a1), fminf(b0, b1));
        float mx = fmaxf(fmaxf(a0, a1), fmaxf(b0, b1));
#pragma unroll
        for (int o = 16; o; o >>= 1) {
            mn = fminf(mn, __shfl_xor_sync(0xffffffffu, mn, o));
            mx = fmaxf(mx, __shfl_xor_sync(0xffffffffu, mx, o));
        }
        if (lane == 0) { bounds[2 * w] = mn; bounds[2 * w + 1] = mx; }
    }

    const float beta = beta_p[0];
    const float sig  = __expf(logsig_p[0]);
    const float c2   = (0.5f / (sig * sig)) * LOG2E_F;

    for (int j = t; j < JCH; j += 192) {
        int jj = jc * JCH + j;
        sxa[j]  = hist[b * (HH * 2) + 2 * jj];
        sya[j]  = hist[b * (HH * 2) + 2 * jj + 1];
        sbta[j] = beta * itime[b * HH + jj] * LOG2E_F;
    }
    __syncthreads();

    if (t < NG) {
        float minx = bounds[0], maxx = bounds[1];
        float miny = bounds[2], maxy = bounds[3];
        float fx = (t == NG - 1) ? maxx : minx + (maxx - minx) * ((float)t / (float)(NG - 1));
        float fy = (t == NG - 1) ? maxy : miny + (maxy - miny) * ((float)t / (float)(NG - 1));
        xl[t] = fx; yl[t] = fy;
        if (jc == 0 && b == 0) { g_xlim[t] = fx; g_ylim[t] = fy; }
    }
    __syncthreads();

    for (int e = t; e < JCH * TROW; e += 192) {
        int j = e / TROW, kc = e - j * TROW;
        if (kc < NG) {
            float dx = xl[kc] - sxa[j];
            float dy = yl[kc] - sya[j];
            Bx[e] = ex2f(fmaf(-c2, dx * dx, sbta[j]));
            Ay[e] = ex2f(-c2 * dy * dy);
        } else {
            Bx[e] = 0.f;
            Ay[e] = 0.f;
        }
    }
    __syncthreads();

    if (t < 175) {
        const int tx = t % 7;
        const int ky = t / 7;
        float ac0 = 0.f, ac1 = 0.f, ac2 = 0.f, ac3 = 0.f;
#pragma unroll 4
        for (int j = 0; j < JCH; j++) {
            float4 bx = *(const float4*)&Bx[j * TROW + tx * 4];
            float  ay = Ay[j * TROW + ky];
            ac0 = fmaf(bx.x, ay, ac0);
            ac1 = fmaf(bx.y, ay, ac1);
            ac2 = fmaf(bx.z, ay, ac2);
            ac3 = fmaf(bx.w, ay, ac3);
        }
        int kx = tx * 4;
        float* dst = &g_Spart[jc][b * CAND + ky * NG + kx];
        dst[0] = ac0;
        if (kx + 1 < NG) dst[1] = ac1;
        if (kx + 2 < NG) dst[2] = ac2;
        if (kx + 3 < NG) dst[3] = ac3;
    }
}

// ---------------------------------------------------------------------------
// Kernel 2: fused argmin-loop + GMM loglik. One block per batch, 512 threads.
// WARP SPECIALIZATION: warp 0 runs the 16-step sequential argmin (20 cands per
// lane in registers, zero barriers, redux.sync.min two-phase -> exact
// first-index tie-break) while warps 1..15 CONCURRENTLY compute the GMM
// triangle rows 1..383 (history-only, independent of predictions).
// Then one __syncthreads, 16 tail rows (384..399, involve predictions),
// warp-acc reduce, single out[b] write.
//   logp_i = log(sum_{j<i} e_j * g_ij) - log(sum_{j<i} e_j) - C  (e^{-bt_i}
//   cancels), pair term = 1 LDS.128 (px,py,bt,e) + 7 fma + 1 MUFU.
// ---------------------------------------------------------------------------
__global__ __launch_bounds__(512, 1)
void k_fuse(const float* __restrict__ curr,
            const float* __restrict__ itime,
            const float* __restrict__ hist,
            const float* __restrict__ beta_p,
            const float* __restrict__ logsig_p,
            float* __restrict__ out) {
    __shared__ __align__(16) float4 tab[LF];   // (px, py, bt, e) per point
    __shared__ float xl[NG], yl[NG];
    __shared__ float sct[NPLT];
    __shared__ float wacc[16];

    const int b = blockIdx.x;
    const int t = threadIdx.x;   // 512
    const int w = t >> 5, lane = t & 31;

    const float beta = beta_p[0];
    const float ls   = logsig_p[0];
    const float sig  = __expf(ls);
    const float c2   = (0.5f / (sig * sig)) * LOG2E_F;

    // ---- stage: history table, grids, curr times ----
    if (t < HH) {
        float hx = hist[b * (HH * 2) + 2 * t];
        float hy = hist[b * (HH * 2) + 2 * t + 1];
        float bt = beta * itime[b * HH + t] * LOG2E_F;
        tab[t] = make_float4(hx, hy, bt, ex2f(bt));
    } else if (t < HH + NG) {
        int q = t - HH;
        xl[q] = g_xlim[q];
        yl[q] = g_ylim[q];
    } else if (t >= HH + 32 && t < HH + 32 + NPLT) {
        int q = t - HH - 32;
        sct[q] = curr[b * NPLT + q];
    }

    // warp 0: preload S (sum of 4 partials) into registers (before barrier;
    // g_Spart comes from the previous kernel, no intra-block dependency)
    const int NR = 20;
    float s[NR];
    if (w == 0) {
#pragma unroll
        for (int r = 0; r < NR; r++) {
            int k = lane + 32 * r;
            if (k < CAND) {
                s[r] = g_Spart[0][b * CAND + k] + g_Spart[1][b * CAND + k]
                     + g_Spart[2][b * CAND + k] + g_Spart[3][b * CAND + k];
            } else {
                s[r] = 0.f;
            }
        }
    }
    __syncthreads();

    float acc = 0.f;

    if (w == 0) {
        // ================= sequential argmin loop (warp 0 only) ============
        float cx[NR], cy[NR];
#pragma unroll
        for (int r = 0; r < NR; r++) {
            int k = lane + 32 * r;
            cx[r] = (k < CAND) ? xl[k % NG] : 0.f;
            cy[r] = (k < CAND) ? yl[k / NG] : 0.f;
        }

        for (int i = 0; i < NPLT; i++) {
            // phase 1: min S bits (S >= 0 -> bits order-preserving)
            unsigned vb = 0xFFFFFFFFu;
#pragma unroll
            for (int r = 0; r < NR; r++) {
                int k = lane + 32 * r;
                if (k < CAND) {
                    unsigned u = __float_as_uint(s[r]);
                    vb = (u < vb) ? u : vb;
                }
            }
            unsigned gmin = redux_min_u32(vb);
            // phase 2: min index among equals -> first-index tie-break
            unsigned ki = 0xFFFFFFFFu;
#pragma unroll
            for (int r = NR - 1; r >= 0; r--) {
                int k = lane + 32 * r;
                if (k < CAND && __float_as_uint(s[r]) == gmin) ki = (unsigned)k;
            }
            unsigned idx = redux_min_u32(ki);

            float px = xl[idx % NG];
            float py = yl[idx / NG];
            float bti = beta * sct[i] * LOG2E_F;
            if (lane == 0) {
                out[BB + (i * BB + b) * 2 + 0] = px;
                out[BB + (i * BB + b) * 2 + 1] = py;
                tab[HH + i] = make_float4(px, py, bti, ex2f(bti));
            }
            if (i < NPLT - 1) {
#pragma unroll
                for (int r = 0; r < NR; r++) {
                    float dx = cx[r] - px;
                    float dy = cy[r] - py;
                    s[r] += ex2f(fmaf(-c2, fmaf(dx, dx, dy * dy), bti));
                }
            }
        }
    } else {
        // ============ GMM triangle rows 1..383 (warps 1..15) ===============
        for (int i = w; i < HH; i += 15) {
            float4 pi = tab[i];
            float s1 = 0.f, s2 = 0.f;
            for (int j = lane; j < i; j += 32) {
                float4 pj = tab[j];
                float dx = pi.x - pj.x;
                float dy = pi.y - pj.y;
                float sq = fmaf(dx, dx, dy * dy);
                s1 += pj.w;
                s2 += ex2f(fmaf(-c2, sq, pj.z));
            }
#pragma unroll
            for (int o = 16; o; o >>= 1) {
                s1 += __shfl_down_sync(0xffffffffu, s1, o);
                s2 += __shfl_down_sync(0xffffffffu, s2, o);
            }
            if (lane == 0) acc += __logf(s2) - __logf(s1);
        }
    }
    __syncthreads();  // preds in tab[HH..] visible; triangle done

    // ---- tail rows 384..399: warp w handles row HH + w ----
    {
        int i = HH + w;
        float4 pi = tab[i];
        float s1 = 0.f, s2 = 0.f;
        for (int j = lane; j < i; j += 32) {
            float4 pj = tab[j];
            float dx = pi.x - pj.x;
            float dy = pi.y - pj.y;
            float sq = fmaf(dx, dx, dy * dy);
            s1 += pj.w;
            s2 += ex2f(fmaf(-c2, sq, pj.z));
        }
#pragma unroll
        for (int o = 16; o; o >>= 1) {
            s1 += __shfl_down_sync(0xffffffffu, s1, o);
            s2 += __shfl_down_sync(0xffffffffu, s2, o);
        }
        if (lane == 0) acc += __logf(s2) - __logf(s1);
    }
    if (lane == 0) wacc[w] = acc;
    __syncthreads();

    if (t == 0) {
        float tot = 0.f;
#pragma unroll
        for (int q = 0; q < 16; q++) tot += wacc[q];
        float C = 2.f * ls + LOG2PI_F;
        float4 p0 = tab[0];
        float logp0 = -0.5f * (p0.x * p0.x + p0.y * p0.y) - LOG2PI_F;
        out[b] = logp0 + tot - (float)(LF - 1) * C;
    }
}

// ---------------------------------------------------------------------------
extern "C" void kernel_launch(void* const* d_in, const int* in_sizes, int n_in,
                              void* d_out, int out_size) {
    const float* curr   = (const float*)d_in[0];  // (64,16)
    const float* itime  = (const float*)d_in[1];  // (64,384)
    const float* hist   = (const float*)d_in[2];  // (64,384,2)
    // d_in[3..5] (expected_data, aux_*) are dead inputs
    const float* beta   = (const float*)d_in[6];
    const float* logsig = (const float*)d_in[7];
    float* out = (float*)d_out;  // [64 loglik][16*64*2 predicted]

    k_base<<<dim3(JS, BB), 192>>>(itime, hist, beta, logsig);
    k_fuse<<<BB, 512>>>(curr, itime, hist, beta, logsig, out);
}